// round 14
// baseline (speedup 1.0000x reference)
#include <cuda_runtime.h>
#include <cstdint>

// Problem constants
#define NB   8
#define TPD  2048
#define ED   4096
#define TD   16384
#define VD   17
#define OUTROWS 131072
#define KT   64             // K floats per pipeline stage
#define NSTG (ED / KT)      // 64 stages
#define MTIL 128            // bucket rows per block
#define RMAX 16384

typedef unsigned long long ull;

// Scratch (device globals)
__device__ float g_WeffJ[64 * ED];      // [j=s0*8+s][e], tf32-rounded
__device__ float g_beff[8];             // includes b2
__device__ int   g_bucket[64 * 2048];   // [(n*8+s0)][slot] = (rank<<16)|tp
__device__ int   g_bcount[64];
__device__ int   g_count8[NB];          // 8 * per-batch masked count

// ---------------------------------------------------------------------------
// helpers
// ---------------------------------------------------------------------------
__device__ __forceinline__ void ldgsts16(void* dst, const void* src) {
    unsigned saddr = (unsigned)__cvta_generic_to_shared(dst);
    asm volatile("cp.async.cg.shared.global [%0], [%1], 16;\n" :: "r"(saddr), "l"(src));
}
__device__ __forceinline__ void cp_commit() {
    asm volatile("cp.async.commit_group;\n" ::: "memory");
}
template <int N>
__device__ __forceinline__ void cp_wait() {
    asm volatile("cp.async.wait_group %0;\n" :: "n"(N) : "memory");
}
__device__ __forceinline__ float to_tf32_rna(float f) {
    unsigned u;
    asm("cvt.rna.tf32.f32 %0, %1;" : "=r"(u) : "f"(f));
    return __uint_as_float(u);
}
// XOR-swizzled index into 64-float (2 x 32-float srow) rows
__device__ __forceinline__ int idx64(int row, int col) {
    int sr = row * 2 + (col >> 5);
    int c32 = col & 31;
    return sr * 32 + ((((c32 >> 2) ^ (sr & 7)) << 2) | (c32 & 3));
}
__device__ __forceinline__ void mma_tf32(float* c, const unsigned* a,
                                         unsigned b0, unsigned b1) {
    asm volatile(
        "mma.sync.aligned.m16n8k8.row.col.f32.tf32.tf32.f32 "
        "{%0,%1,%2,%3}, {%4,%5,%6,%7}, {%8,%9}, {%0,%1,%2,%3};"
        : "+f"(c[0]), "+f"(c[1]), "+f"(c[2]), "+f"(c[3])
        : "r"(a[0]), "r"(a[1]), "r"(a[2]), "r"(a[3]), "r"(b0), "r"(b1));
}

// ---------------------------------------------------------------------------
// K01 fused, 1024 threads/block (R8-proven prep + plain WeffJ):
//   blocks [0,8): per-batch argmax + bucketed compaction (coalesced int4,
//                 4 passes, carried scan bases); payload (rank<<16)|tp
//   blocks [8,264): WeffJ rows for 16 e-values each (+beff at block 8)
// ---------------------------------------------------------------------------
__global__ __launch_bounds__(1024) void k01(const float* __restrict__ W1,
                                            const float* __restrict__ W2,
                                            const float* __restrict__ b1,
                                            const float* __restrict__ b2,
                                            const int* __restrict__ value,
                                            const int* __restrict__ depth) {
    int bid = blockIdx.x;
    int tid = threadIdx.x;

    if (bid >= 8) {
        // ---- WeffJ: 16 e-values per block ----
        __shared__ __align__(16) float w2s[512];
        __shared__ __align__(16) float w1r[16][512];
        int e0 = (bid - 8) * 16;
        if (tid < 128) ((float4*)w2s)[tid] = ((const float4*)W2)[tid];
        ((float4*)&w1r[0][0])[tid]        = ((const float4*)(W1 + (size_t)e0 * 512))[tid];
        ((float4*)&w1r[0][0])[tid + 1024] = ((const float4*)(W1 + (size_t)e0 * 512))[tid + 1024];
        __syncthreads();
        int sub = tid >> 6;       // which e (0..15)
        int t64 = tid & 63;
        int s0 = t64 >> 3, s = t64 & 7;
        int e = e0 + sub;
        float acc = 0.f;
#pragma unroll
        for (int c = 0; c < 64; c++) acc += w1r[sub][c * 8 + s0] * w2s[c * 8 + s];
        g_WeffJ[(size_t)(s0 * 8 + s) * ED + e] = to_tf32_rna(acc);
        if (bid == 8 && tid < 8) {
            float a = 0.f;
#pragma unroll
            for (int c = 0; c < 64; c++) a += b1[c] * w2s[c * 8 + tid];
            g_beff[tid] = a + b2[0];
        }
    } else {
        // ---- prep: batch n, 1024 threads, coalesced int4, 4 passes ----
        int n = bid;
        const int* dep = depth + n * TD;
        const int* val = value + n * TD;
        __shared__ int s_idx;
        __shared__ int wsum[32];
        __shared__ ull wtA[32], wtB[32];
        __shared__ int wbase[32 * 8];
        __shared__ int sb_r;
        __shared__ int sb_s0[8];
        __shared__ int pass_tot;
        __shared__ int pass_tot_s0[8];

        int lane = tid & 31, wid = tid >> 5;  // 32 warps

        int maxv = dep[TD - 1];
        if (tid == 0) { s_idx = TD; sb_r = 0; }
        if (tid < 8) sb_s0[tid] = 0;
        __syncthreads();
        for (int t0 = tid * 4; t0 < TD; t0 += 4096) {
            int4 d = *(const int4*)(dep + t0);
            int prev = (t0 == 0) ? (maxv - 1) : dep[t0 - 1];
            if (d.x == maxv && prev < maxv) atomicMin(&s_idx, t0);
            if (d.y == maxv && d.x < maxv) atomicMin(&s_idx, t0 + 1);
            if (d.z == maxv && d.y < maxv) atomicMin(&s_idx, t0 + 2);
            if (d.w == maxv && d.z < maxv) atomicMin(&s_idx, t0 + 3);
        }
        __syncthreads();
        int idx = s_idx;
        int bb = n * 8;

        for (int pass = 0; pass < 4; pass++) {
            int t0 = pass * 4096 + tid * 4;
            int4 vv = *(const int4*)(val + t0);
            int vj[4] = {vv.x, vv.y, vv.z, vv.w};
            unsigned mb = 0;
            int cnt = 0;
            ull cA = 0, cB = 0;  // per-s0 counts, 16-bit fields (s0 0-3 / 4-7)
#pragma unroll
            for (int j = 0; j < 4; j++) {
                int t = t0 + j;
                bool m = (t < idx) && (vj[j] == 2);
                mb |= ((unsigned)m) << j;
                cnt += (int)m;
                if (m) {
                    int f = t & 7;
                    if (f < 4) cA += 1ull << (f * 16);
                    else       cB += 1ull << ((f - 4) * 16);
                }
            }
            int v = cnt;
            ull ciA = cA, ciB = cB;
#pragma unroll
            for (int o = 1; o < 32; o <<= 1) {
                int u  = __shfl_up_sync(0xffffffffu, v, o);
                ull uA = __shfl_up_sync(0xffffffffu, ciA, o);
                ull uB = __shfl_up_sync(0xffffffffu, ciB, o);
                if (lane >= o) { v += u; ciA += uA; ciB += uB; }
            }
            if (lane == 31) { wsum[wid] = v; wtA[wid] = ciA; wtB[wid] = ciB; }
            __syncthreads();
            if (wid == 0) {
                int w = wsum[lane];
                int wi = w;
#pragma unroll
                for (int o = 1; o < 32; o <<= 1) {
                    int u = __shfl_up_sync(0xffffffffu, wi, o);
                    if (lane >= o) wi += u;
                }
                wsum[lane] = wi - w;
                if (lane == 31) pass_tot = wi;
            } else if (wid == 1 && lane < 8) {
                int s0 = lane;
                int run = 0;
#pragma unroll
                for (int w = 0; w < 32; w++) {
                    int c = (s0 < 4) ? (int)((wtA[w] >> (s0 * 16)) & 0xFFFF)
                                     : (int)((wtB[w] >> ((s0 - 4) * 16)) & 0xFFFF);
                    wbase[w * 8 + s0] = run;
                    run += c;
                }
                pass_tot_s0[s0] = run;
            }
            __syncthreads();
            int r = sb_r + wsum[wid] + (v - cnt);
            ull exA = ciA - cA, exB = ciB - cB;
#pragma unroll
            for (int j = 0; j < 4; j++) {
                if ((mb >> j) & 1u) {
                    int t = t0 + j;
                    int s0 = t & 7;
                    int ex = (s0 < 4) ? (int)((exA >> (s0 * 16)) & 0xFFFF)
                                      : (int)((exB >> ((s0 - 4) * 16)) & 0xFFFF);
                    int slot = sb_s0[s0] + wbase[wid * 8 + s0] + ex;
                    g_bucket[(bb + s0) * 2048 + slot] = (r << 16) | (t >> 3);
                    if (s0 < 4) exA += 1ull << (s0 * 16);
                    else        exB += 1ull << ((s0 - 4) * 16);
                    r++;
                }
            }
            __syncthreads();
            if (tid == 0) sb_r += pass_tot;
            if (tid < 8) sb_s0[tid] += pass_tot_s0[tid];
            __syncthreads();
        }
        if (tid < 8) g_bcount[bb + tid] = sb_s0[tid];
        if (tid == 0) g_count8[n] = 8 * sb_r;
    }
}

// ---------------------------------------------------------------------------
// K3_BKT: bucketed tf32 mma GEMM, full-K (no partials), fused epilogue.
//   Block (ch*8+s0, n): rows = bucket[(n,s0)] entries [ch*128, +128),
//   N = 8 (the 8 s of this s0), K = 4096: 64 double-buffered KT=64 stages.
//   128 threads = 4 warps, warp tile m32n8. XOR-swizzled smem.
//   Epilogue: out[n, rank*8+s, v] = (acc + beff[s]) * W3[v]  (544B per entry).
// ---------------------------------------------------------------------------
__global__ __launch_bounds__(128) void k3_bkt(const float* __restrict__ x,
                                              const float* __restrict__ W3,
                                              float* __restrict__ out) {
    int bx = blockIdx.x;
    int s0 = bx & 7, ch = bx >> 3;
    int n = blockIdx.y;
    int bucket = n * 8 + s0;
    int bcnt = g_bcount[bucket];
    int row0 = ch * MTIL;
    if (row0 >= bcnt) return;
    int tid = threadIdx.x;
    int w = tid >> 5, lane = tid & 31;
    int gid = lane >> 2, tig = lane & 3;

    __shared__ __align__(16) float As[2][MTIL * KT];  // 2 x 32KB
    __shared__ __align__(16) float Bs[2][8 * KT];     // 2 x 2KB
    __shared__ float y2s[MTIL][8];
    __shared__ int stp_s[MTIL];
    __shared__ int rk_s[MTIL];
    __shared__ float w3s[VD];
    __shared__ float beffs[8];

    // prologue: entries + constants
    {
        int gr = row0 + tid;
        if (gr < bcnt) {
            int p = g_bucket[bucket * 2048 + gr];
            rk_s[tid]  = p >> 16;
            stp_s[tid] = p & 0xFFFF;
        } else {
            rk_s[tid] = -1;
            stp_s[tid] = 0;
        }
        if (tid < VD) w3s[tid] = W3[tid];
        if (tid < 8) beffs[tid] = g_beff[tid];
    }
    __syncthreads();

    const float* xb = x + (size_t)n * TPD * ED;
    const float* wb = g_WeffJ + (size_t)(s0 * 8) * ED;

    // stage loader: A 128 rows x 256B (16 chunks/row, 16 lanes cover a row),
    // B 8 rows x 256B. XOR swizzle per 32-float srow.
    auto load_stage = [&](int st, int b) {
        int kbase = st * KT;
#pragma unroll
        for (int p = 0; p < 16; p++) {
            int g = p * 128 + tid;
            int r = g >> 4, c = g & 15;
            int sr = r * 2 + (c >> 3), cc = c & 7;
            ldgsts16(&As[b][sr * 32 + ((cc ^ (sr & 7)) << 2)],
                     xb + (size_t)stp_s[r] * ED + kbase + c * 4);
        }
        {
            int r = tid >> 4, c = tid & 15;
            int sr = r * 2 + (c >> 3), cc = c & 7;
            ldgsts16(&Bs[b][sr * 32 + ((cc ^ (sr & 7)) << 2)],
                     wb + (size_t)r * ED + kbase + c * 4);
        }
        cp_commit();
    };

    load_stage(0, 0);

    float acc[2][4];
#pragma unroll
    for (int i = 0; i < 2; i++)
#pragma unroll
        for (int q = 0; q < 4; q++) acc[i][q] = 0.f;

    for (int st = 0; st < NSTG; st++) {
        int b = st & 1;
        if (st + 1 < NSTG) {
            load_stage(st + 1, b ^ 1);
            cp_wait<1>();
        } else {
            cp_wait<0>();
        }
        __syncthreads();

#pragma unroll
        for (int kk = 0; kk < 8; kk++) {
            int c0 = kk * 8 + tig;
            unsigned b0 = __float_as_uint(Bs[b][idx64(gid, c0)]);
            unsigned b1 = __float_as_uint(Bs[b][idx64(gid, c0 + 4)]);
#pragma unroll
            for (int i = 0; i < 2; i++) {
                int rl = w * 32 + i * 16 + gid;
                unsigned a[4];
                a[0] = __float_as_uint(As[b][idx64(rl, c0)]);
                a[1] = __float_as_uint(As[b][idx64(rl + 8, c0)]);
                a[2] = __float_as_uint(As[b][idx64(rl, c0 + 4)]);
                a[3] = __float_as_uint(As[b][idx64(rl + 8, c0 + 4)]);
                mma_tf32(acc[i], a, b0, b1);
            }
        }
        __syncthreads();
    }

    // epilogue: stage y2 (+beff), then coalesced 544B-per-entry stores
#pragma unroll
    for (int i = 0; i < 2; i++) {
        int m = w * 32 + i * 16 + gid;
        y2s[m][2 * tig]         = acc[i][0] + beffs[2 * tig];
        y2s[m][2 * tig + 1]     = acc[i][1] + beffs[2 * tig + 1];
        y2s[m + 8][2 * tig]     = acc[i][2] + beffs[2 * tig];
        y2s[m + 8][2 * tig + 1] = acc[i][3] + beffs[2 * tig + 1];
    }
    __syncthreads();

    float* ob = out + (size_t)n * OUTROWS * VD;
    // 136 floats (= 34 float4) per entry at out row rank*8
    for (int f = tid; f < MTIL * 34; f += 128) {
        int m = f / 34, q = f - m * 34;
        int rr = rk_s[m];
        if (rr < 0) continue;
        float4 o;
#pragma unroll
        for (int c = 0; c < 4; c++) {
            int pos = q * 4 + c;
            int ss = pos / VD, vv = pos - ss * VD;
            ((float*)&o)[c] = y2s[m][ss] * w3s[vv];
        }
        *(float4*)(ob + (size_t)rr * 136 + q * 4) = o;
    }
}

// ---------------------------------------------------------------------------
// K5: tail fill. Rows j >= count8 get b2*W3[v]; heavy rows untouched (k3 owns).
// ---------------------------------------------------------------------------
__global__ __launch_bounds__(256) void k5_fill(const float* __restrict__ W3,
                                               const float* __restrict__ b2,
                                               float* __restrict__ out) {
    int n = blockIdx.y;
    int count8 = g_count8[n];
    int j0 = blockIdx.x * 256;
    if (j0 + 256 <= count8) return;
    int tid = threadIdx.x;
    __shared__ float w3s[VD];
    if (tid < VD) w3s[tid] = W3[tid];
    __syncthreads();
    float bv = b2[0];

    float* ob = out + ((size_t)n * OUTROWS + j0) * VD;
    const int NF4 = 256 * VD / 4;  // 1088
    for (int f = tid; f < NF4; f += 256) {
        int idx = f * 4;
        int jfirst = j0 + idx / VD;
        int jlast = j0 + (idx + 3) / VD;
        if (jlast < count8) continue;
        float4 o;
#pragma unroll
        for (int c = 0; c < 4; c++) {
            int p = idx + c;
            int vv = p % VD;
            ((float*)&o)[c] = bv * w3s[vv];
        }
        if (jfirst >= count8) {
            *(float4*)(ob + idx) = o;
        } else {
            // boundary straddle: scalar stores for tail components only
#pragma unroll
            for (int c = 0; c < 4; c++) {
                int p = idx + c;
                if (j0 + p / VD >= count8) ob[p] = ((float*)&o)[c];
            }
        }
    }
}

// ---------------------------------------------------------------------------
extern "C" void kernel_launch(void* const* d_in, const int* in_sizes, int n_in,
                              void* d_out, int out_size) {
    const float* x     = (const float*)d_in[0];
    const int*   value = (const int*)d_in[1];   // jax x64-off: int32
    const int*   depth = (const int*)d_in[2];
    // d_in[3] = pos, unused
    const float* W1    = (const float*)d_in[4];
    const float* b1    = (const float*)d_in[5];
    const float* W2    = (const float*)d_in[6];
    const float* b2    = (const float*)d_in[7];
    const float* W3    = (const float*)d_in[8];
    float* out = (float*)d_out;

    k01<<<264, 1024>>>(W1, W2, b1, b2, value, depth);
    k3_bkt<<<dim3(16 * 8, NB), 128>>>(x, W3, out);
    k5_fill<<<dim3(OUTROWS / 256, NB), 256>>>(W3, b2, out);
}

// round 15
// speedup vs baseline: 1.5318x; 1.5318x over previous
#include <cuda_runtime.h>
#include <cstdint>

// Problem constants
#define NB   8
#define TPD  2048
#define ED   4096
#define TD   16384
#define VD   17
#define OUTROWS 131072
#define KSP  4              // K splits for the GEMM
#define KC   (ED / KSP)     // 1024 K per block
#define KT   32             // K floats per pipeline stage (128B rows)
#define NSTG (KC / KT)      // 32 stages
#define MTIL 256            // M rows per block
#define RMAX 16384

typedef unsigned long long ull;

// Scratch (device globals)
__device__ float g_WeffJ[64 * ED];            // [j=s0*8+s][e], tf32-rounded
__device__ float g_beff[8];
__device__ unsigned short g_entry[NB * RMAX]; // per-batch sorted masked t (rank = index)
__device__ int   g_count8[NB];                // 8 * per-batch masked count
__device__ float g_C[(size_t)KSP * NB * TPD * 64];  // dense GEMM partials (16MB)

// ---------------------------------------------------------------------------
// helpers
// ---------------------------------------------------------------------------
__device__ __forceinline__ void ldgsts16(void* dst, const void* src) {
    unsigned saddr = (unsigned)__cvta_generic_to_shared(dst);
    asm volatile("cp.async.cg.shared.global [%0], [%1], 16;\n" :: "r"(saddr), "l"(src));
}
__device__ __forceinline__ void cp_commit() {
    asm volatile("cp.async.commit_group;\n" ::: "memory");
}
template <int N>
__device__ __forceinline__ void cp_wait() {
    asm volatile("cp.async.wait_group %0;\n" :: "n"(N) : "memory");
}
__device__ __forceinline__ float to_tf32_rna(float f) {
    unsigned u;
    asm("cvt.rna.tf32.f32 %0, %1;" : "=r"(u) : "f"(f));
    return __uint_as_float(u);
}
// XOR-swizzled smem float index: 32-float (128B) rows, 16B chunk swizzle
__device__ __forceinline__ int aidx(int r, int ce) {
    return r * 32 + ((((ce >> 2) ^ (r & 7)) << 2) | (ce & 3));
}
__device__ __forceinline__ void mma_tf32(float* c, const unsigned* a,
                                         unsigned b0, unsigned b1) {
    asm volatile(
        "mma.sync.aligned.m16n8k8.row.col.f32.tf32.tf32.f32 "
        "{%0,%1,%2,%3}, {%4,%5,%6,%7}, {%8,%9}, {%0,%1,%2,%3};"
        : "+f"(c[0]), "+f"(c[1]), "+f"(c[2]), "+f"(c[3])
        : "r"(a[0]), "r"(a[1]), "r"(a[2]), "r"(a[3]), "r"(b0), "r"(b1));
}

// ---------------------------------------------------------------------------
// K01: WeffJ only. 256 blocks x 1024 threads, 16 e-values each (+beff at 0).
// ---------------------------------------------------------------------------
__global__ __launch_bounds__(1024) void k01_weff(const float* __restrict__ W1,
                                                 const float* __restrict__ W2,
                                                 const float* __restrict__ b1,
                                                 const float* __restrict__ b2) {
    int bid = blockIdx.x;
    int tid = threadIdx.x;
    __shared__ __align__(16) float w2s[512];
    __shared__ __align__(16) float w1r[16][512];
    int e0 = bid * 16;
    if (tid < 128) ((float4*)w2s)[tid] = ((const float4*)W2)[tid];
    ((float4*)&w1r[0][0])[tid]        = ((const float4*)(W1 + (size_t)e0 * 512))[tid];
    ((float4*)&w1r[0][0])[tid + 1024] = ((const float4*)(W1 + (size_t)e0 * 512))[tid + 1024];
    __syncthreads();
    int sub = tid >> 6;       // which e (0..15)
    int t64 = tid & 63;
    int s0 = t64 >> 3, s = t64 & 7;
    int e = e0 + sub;
    float acc = 0.f;
#pragma unroll
    for (int c = 0; c < 64; c++) acc += w1r[sub][c * 8 + s0] * w2s[c * 8 + s];
    g_WeffJ[(size_t)(s0 * 8 + s) * ED + e] = to_tf32_rna(acc);
    if (bid == 0 && tid < 8) {
        float a = 0.f;
#pragma unroll
        for (int c = 0; c < 64; c++) a += b1[c] * w2s[c * 8 + tid];
        g_beff[tid] = a + b2[0];
    }
}

// ---------------------------------------------------------------------------
// Prep (run inside k3's grid, 128 threads): per-batch argmax + masked
// compaction into a single rank-ordered t list. 32 passes of 512 elems.
// ---------------------------------------------------------------------------
__device__ void prep_batch(int n, const int* __restrict__ value,
                           const int* __restrict__ depth) {
    int tid = threadIdx.x;
    const int* dep = depth + n * TD;
    const int* val = value + n * TD;
    __shared__ int s_idx;
    __shared__ int wsum[4];
    __shared__ int sb_r;
    __shared__ int pass_tot;

    int lane = tid & 31, wid = tid >> 5;  // 4 warps

    int maxv = dep[TD - 1];
    if (tid == 0) { s_idx = TD; sb_r = 0; }
    __syncthreads();
    for (int t0 = tid * 4; t0 < TD; t0 += 512) {
        int4 d = *(const int4*)(dep + t0);
        int prev = (t0 == 0) ? (maxv - 1) : dep[t0 - 1];
        if (d.x == maxv && prev < maxv) atomicMin(&s_idx, t0);
        if (d.y == maxv && d.x < maxv) atomicMin(&s_idx, t0 + 1);
        if (d.z == maxv && d.y < maxv) atomicMin(&s_idx, t0 + 2);
        if (d.w == maxv && d.z < maxv) atomicMin(&s_idx, t0 + 3);
    }
    __syncthreads();
    int idx = s_idx;

    for (int pass = 0; pass < 32; pass++) {
        int t0 = pass * 512 + tid * 4;
        int4 vv = *(const int4*)(val + t0);
        int vj[4] = {vv.x, vv.y, vv.z, vv.w};
        unsigned mb = 0;
        int cnt = 0;
#pragma unroll
        for (int j = 0; j < 4; j++) {
            int t = t0 + j;
            bool m = (t < idx) && (vj[j] == 2);
            mb |= ((unsigned)m) << j;
            cnt += (int)m;
        }
        int v = cnt;
#pragma unroll
        for (int o = 1; o < 32; o <<= 1) {
            int u = __shfl_up_sync(0xffffffffu, v, o);
            if (lane >= o) v += u;
        }
        if (lane == 31) wsum[wid] = v;
        __syncthreads();
        if (tid == 0) {
            int run = 0;
#pragma unroll
            for (int w = 0; w < 4; w++) { int t = wsum[w]; wsum[w] = run; run += t; }
            pass_tot = run;
        }
        __syncthreads();
        int r = sb_r + wsum[wid] + (v - cnt);
#pragma unroll
        for (int j = 0; j < 4; j++) {
            if ((mb >> j) & 1u) {
                g_entry[n * RMAX + r] = (unsigned short)(t0 + j);
                r++;
            }
        }
        __syncthreads();
        if (tid == 0) sb_r += pass_tot;
        __syncthreads();
    }
    if (tid == 0) g_count8[n] = 8 * sb_r;
}

// ---------------------------------------------------------------------------
// K3_MMA: dense tf32 mma.sync GEMM (R13-proven core), warp tile m64n64.
//   MMA blocks (mt<8, ksp, n): C_part[ksp][n][mt*256..+256][0..64)
//     = X[256 rows, KC] · WeffJ[64 rows, KC]^T
//   Extra x-slot mt==8, ksp==0: prep block for batch n (runs concurrently;
//   its outputs are consumed only by k4).
// ---------------------------------------------------------------------------
__global__ __launch_bounds__(128) void k3_mma(const float* __restrict__ x,
                                              const int* __restrict__ value,
                                              const int* __restrict__ depth) {
    int mt = blockIdx.x, ksp = blockIdx.y, n = blockIdx.z;
    if (mt == 8) {
        if (ksp == 0) prep_batch(n, value, depth);
        return;
    }
    int tid = threadIdx.x;
    int w = tid >> 5, lane = tid & 31;
    int gid = lane >> 2, tig = lane & 3;

    extern __shared__ __align__(16) float dsm[];
    float* As = dsm;                 // [2][256*32] = 65536B
    float* Bs = dsm + 2 * 256 * 32;  // [2][64*32]  = 16384B

    const float* xb = x + (((size_t)n * TPD) + mt * MTIL) * ED + ksp * KC;
    const float* wb = g_WeffJ + ksp * KC;

    auto load_stage = [&](int st, int b) {
        const float* xs = xb + st * KT;
        float* Ab = As + b * 256 * 32;
#pragma unroll
        for (int p = 0; p < 16; p++) {
            int g = p * 128 + tid;
            int r = g >> 3, c = g & 7;          // 8 x 16B chunks per 128B row
            ldgsts16(&Ab[r * 32 + ((c ^ (r & 7)) << 2)],
                     xs + (size_t)r * ED + c * 4);
        }
        const float* ws = wb + st * KT;
        float* Bb = Bs + b * 64 * 32;
#pragma unroll
        for (int p = 0; p < 4; p++) {
            int g = p * 128 + tid;
            int r = g >> 3, c = g & 7;
            ldgsts16(&Bb[r * 32 + ((c ^ (r & 7)) << 2)],
                     ws + (size_t)r * ED + c * 4);
        }
        cp_commit();
    };

    load_stage(0, 0);

    float acc[4][8][4];
#pragma unroll
    for (int i = 0; i < 4; i++)
#pragma unroll
        for (int nj = 0; nj < 8; nj++)
#pragma unroll
            for (int q = 0; q < 4; q++) acc[i][nj][q] = 0.f;

    for (int st = 0; st < NSTG; st++) {
        int b = st & 1;
        if (st + 1 < NSTG) {
            load_stage(st + 1, b ^ 1);
            cp_wait<1>();
        } else {
            cp_wait<0>();
        }
        __syncthreads();

        const float* Ab = As + b * 256 * 32;
        const float* Bb = Bs + b * 64 * 32;
#pragma unroll
        for (int kk = 0; kk < 4; kk++) {
            int c0 = kk * 8 + tig;
            unsigned a[4][4];
#pragma unroll
            for (int i = 0; i < 4; i++) {
                int rl = w * 64 + i * 16 + gid;
                int rh = rl + 8;
                a[i][0] = __float_as_uint(Ab[aidx(rl, c0)]);
                a[i][1] = __float_as_uint(Ab[aidx(rh, c0)]);
                a[i][2] = __float_as_uint(Ab[aidx(rl, c0 + 4)]);
                a[i][3] = __float_as_uint(Ab[aidx(rh, c0 + 4)]);
            }
#pragma unroll
            for (int nj = 0; nj < 8; nj++) {
                int j = nj * 8 + gid;
                unsigned b0 = __float_as_uint(Bb[aidx(j, c0)]);
                unsigned b1 = __float_as_uint(Bb[aidx(j, c0 + 4)]);
#pragma unroll
                for (int i = 0; i < 4; i++)
                    mma_tf32(acc[i][nj], a[i], b0, b1);
            }
        }
        __syncthreads();
    }

    // epilogue: scatter C to g_C[ksp][n][tp][64]
    float* cb = g_C + (((size_t)ksp * NB + n) * TPD + (size_t)mt * MTIL) * 64;
#pragma unroll
    for (int i = 0; i < 4; i++) {
        int rl = w * 64 + i * 16 + gid;
#pragma unroll
        for (int nj = 0; nj < 8; nj++) {
            int col = nj * 8 + 2 * tig;
            *(float2*)(cb + (size_t)rl * 64 + col) =
                make_float2(acc[i][nj][0], acc[i][nj][1]);
            *(float2*)(cb + (size_t)(rl + 8) * 64 + col) =
                make_float2(acc[i][nj][2], acc[i][nj][3]);
        }
    }
}

#define K3_SMEM ((2 * 256 * 32 + 2 * 64 * 32) * 4)  // 81920 B

// ---------------------------------------------------------------------------
// K4: gather epilogue + default fill. Strip of 256 output rows per block.
// Heavy rows (j < count8): y2 = sum_ksp C at (tp, s0*8+s) + beff[s].
// ---------------------------------------------------------------------------
__global__ __launch_bounds__(256) void k4_epi(const float* __restrict__ W3,
                                              const float* __restrict__ b2,
                                              float* __restrict__ out) {
    int n = blockIdx.y;
    int j0 = blockIdx.x * 256;
    int tid = threadIdx.x;
    __shared__ float y2s[256];
    __shared__ float w3s[VD];
    __shared__ float beffs[8];
    if (tid < VD) w3s[tid] = W3[tid];
    if (tid < 8) beffs[tid] = g_beff[tid];
    __syncthreads();

    int count8 = g_count8[n];
    int j = j0 + tid;
    float acc;
    if (j < count8) {
        int r = j >> 3, s = j & 7;
        int t = (int)g_entry[n * RMAX + r];
        int tp = t >> 3, s0 = t & 7;
        size_t ci = ((size_t)n * TPD + tp) * 64 + s0 * 8 + s;
        acc = beffs[s];
#pragma unroll
        for (int kq = 0; kq < KSP; kq++)
            acc += g_C[(size_t)kq * NB * TPD * 64 + ci];
    } else {
        acc = b2[0];
    }
    y2s[tid] = acc;
    __syncthreads();

    float* ob = out + ((size_t)n * OUTROWS + j0) * VD;
    const int NF4 = 256 * VD / 4;  // 1088
    for (int f = tid; f < NF4; f += 256) {
        float4 o;
#pragma unroll
        for (int c = 0; c < 4; c++) {
            int idx = f * 4 + c;
            int jj = idx / VD;
            int vv = idx - jj * VD;
            ((float*)&o)[c] = y2s[jj] * w3s[vv];
        }
        *(float4*)(ob + f * 4) = o;
    }
}

// ---------------------------------------------------------------------------
extern "C" void kernel_launch(void* const* d_in, const int* in_sizes, int n_in,
                              void* d_out, int out_size) {
    const float* x     = (const float*)d_in[0];
    const int*   value = (const int*)d_in[1];   // jax x64-off: int32
    const int*   depth = (const int*)d_in[2];
    // d_in[3] = pos, unused
    const float* W1    = (const float*)d_in[4];
    const float* b1    = (const float*)d_in[5];
    const float* W2    = (const float*)d_in[6];
    const float* b2    = (const float*)d_in[7];
    const float* W3    = (const float*)d_in[8];
    float* out = (float*)d_out;

    cudaFuncSetAttribute(k3_mma, cudaFuncAttributeMaxDynamicSharedMemorySize,
                         K3_SMEM);

    k01_weff<<<256, 1024>>>(W1, W2, b1, b2);
    k3_mma<<<dim3(9, KSP, NB), 128, K3_SMEM>>>(x, value, depth);
    k4_epi<<<dim3(OUTROWS / 256, NB), 256>>>(W3, b2, out);
}